// round 1
// baseline (speedup 1.0000x reference)
#include <cuda_runtime.h>
#include <math.h>

#define BB 2
#define SS 1024
#define DD 768
#define HH 12
#define DK 64
#define FF 3072
#define LL 4
#define VV 32000
#define MTOK (BB*SS)   /* 2048 */

// ---------------- scratch (static device globals; no runtime allocation) ---
__device__ float g_h  [MTOK*DD];
__device__ float g_y  [MTOK*DD];
__device__ float g_q  [MTOK*DD];
__device__ float g_k  [MTOK*DD];
__device__ float g_v  [MTOK*DD];
__device__ float g_ctx[MTOK*DD];
__device__ float g_ffn[MTOK*FF];
__device__ int   g_xi [MTOK];

// ---------------- token-id normalization (int64 vs int32 tolerant) --------
__global__ void cvt_x_kernel(const long long* __restrict__ x64) {
    __shared__ int is64;
    if (threadIdx.x == 0) {
        int ok = 1;
        for (int i = 0; i < 16; i++) {
            long long t = x64[i];
            if (t < 0 || t >= VV) ok = 0;
        }
        is64 = ok;
    }
    __syncthreads();
    const int* x32 = (const int*)x64;
    if (is64) {
        for (int i = threadIdx.x; i < MTOK; i += blockDim.x) g_xi[i] = (int)x64[i];
    } else {
        for (int i = threadIdx.x; i < MTOK; i += blockDim.x) g_xi[i] = x32[i];
    }
}

// ---------------- embedding: h = tok_emb[x] + pos_emb[:S] -----------------
__global__ void embed_kernel(const float* __restrict__ tok,
                             const float* __restrict__ pos) {
    int idx = blockIdx.x * blockDim.x + threadIdx.x;
    if (idx < MTOK * DD) {
        int d = idx % DD;
        int t = idx / DD;
        int s = t % SS;
        int tokid = g_xi[t];
        g_h[idx] = tok[tokid * DD + d] + pos[s * DD + d];
    }
}

// ---------------- layernorm (one block per row of 768) --------------------
__global__ void ln_kernel(const float* __restrict__ in,
                          const float* __restrict__ g,
                          const float* __restrict__ b,
                          float* __restrict__ out) {
    int row = blockIdx.x;
    int tid = threadIdx.x;
    const float* xr = in + row * DD;
    __shared__ float r1[256];
    __shared__ float r2[256];
    float s1 = 0.f, s2 = 0.f;
    for (int i = tid; i < DD; i += 256) { float v = xr[i]; s1 += v; s2 += v * v; }
    r1[tid] = s1; r2[tid] = s2;
    __syncthreads();
    for (int o = 128; o > 0; o >>= 1) {
        if (tid < o) { r1[tid] += r1[tid + o]; r2[tid] += r2[tid + o]; }
        __syncthreads();
    }
    float mu  = r1[0] * (1.0f / DD);
    float var = r2[0] * (1.0f / DD) - mu * mu;
    float inv = rsqrtf(var + 1e-5f);
    for (int i = tid; i < DD; i += 256)
        out[row * DD + i] = (xr[i] - mu) * inv * g[i] + b[i];
}

// ---------------- tiled SGEMM: C[M,N] = A[M,K] * B[N,K]^T (+bias,relu,res) -
// Requires M%128==0, N%128==0, K%16==0 (all shapes here satisfy this).
template<bool HASBIAS, bool RELU, bool RES>
__global__ __launch_bounds__(256, 2)
void sgemm_kernel(const float* __restrict__ A, const float* __restrict__ Bm,
                  const float* __restrict__ bias, const float* __restrict__ res,
                  float* __restrict__ C, int M, int N, int K) {
    __shared__ float As[16][128];
    __shared__ float Bs[16][128];
    const int tid = threadIdx.x;
    const int m0 = blockIdx.y * 128;
    const int n0 = blockIdx.x * 128;
    const int tx = tid & 15;      // 0..15 -> N micro
    const int ty = tid >> 4;      // 0..15 -> M micro
    const int row0 = tid >> 2;    // 0..63
    const int cv   = (tid & 3) * 4;

    float acc[8][8];
#pragma unroll
    for (int i = 0; i < 8; i++)
#pragma unroll
        for (int j = 0; j < 8; j++) acc[i][j] = 0.f;

    for (int k0 = 0; k0 < K; k0 += 16) {
#pragma unroll
        for (int s = 0; s < 2; s++) {
            int row = row0 + s * 64;
            float4 av = *(const float4*)&A[(m0 + row) * K + k0 + cv];
            As[cv + 0][row] = av.x; As[cv + 1][row] = av.y;
            As[cv + 2][row] = av.z; As[cv + 3][row] = av.w;
            float4 bv = *(const float4*)&Bm[(n0 + row) * K + k0 + cv];
            Bs[cv + 0][row] = bv.x; Bs[cv + 1][row] = bv.y;
            Bs[cv + 2][row] = bv.z; Bs[cv + 3][row] = bv.w;
        }
        __syncthreads();
#pragma unroll
        for (int kk = 0; kk < 16; kk++) {
            float a[8], bb[8];
#pragma unroll
            for (int i = 0; i < 8; i++) a[i]  = As[kk][ty * 8 + i];
#pragma unroll
            for (int j = 0; j < 8; j++) bb[j] = Bs[kk][tx * 8 + j];
#pragma unroll
            for (int i = 0; i < 8; i++)
#pragma unroll
                for (int j = 0; j < 8; j++)
                    acc[i][j] += a[i] * bb[j];
        }
        __syncthreads();
    }

#pragma unroll
    for (int i = 0; i < 8; i++) {
        int m = m0 + ty * 8 + i;
#pragma unroll
        for (int j = 0; j < 8; j++) {
            int n = n0 + tx * 8 + j;
            float vv = acc[i][j];
            if (HASBIAS) vv += bias[n];
            if (RELU)    vv = fmaxf(vv, 0.f);
            if (RES)     vv += res[m * N + n];
            C[m * N + n] = vv;
        }
    }
}

// ---------------- causal attention: one block per (query row, head, batch) -
__global__ void attn_kernel(const float* __restrict__ q,
                            const float* __restrict__ k,
                            const float* __restrict__ v) {
    const int s = blockIdx.x;
    const int h = blockIdx.y;
    const int b = blockIdx.z;
    const int tid = threadIdx.x;

    __shared__ float qs[DK];
    __shared__ float pr[SS];
    __shared__ float red[128];

    const float* qrow = q + ((b * SS + s) * DD + h * DK);
    if (tid < DK) qs[tid] = qrow[tid];
    __syncthreads();

    // pass 1: scores (causal: j <= s), local max
    float lmax = -1e30f;
    for (int j = tid; j <= s; j += 128) {
        const float4* kr4 = (const float4*)(k + ((b * SS + j) * DD + h * DK));
        float dot = 0.f;
#pragma unroll
        for (int d4 = 0; d4 < 16; d4++) {
            float4 kk4 = kr4[d4];
            dot += qs[d4 * 4 + 0] * kk4.x + qs[d4 * 4 + 1] * kk4.y
                 + qs[d4 * 4 + 2] * kk4.z + qs[d4 * 4 + 3] * kk4.w;
        }
        dot *= 0.125f;  // 1/sqrt(64)
        pr[j] = dot;
        lmax = fmaxf(lmax, dot);
    }
    red[tid] = lmax;
    __syncthreads();
    for (int o = 64; o > 0; o >>= 1) {
        if (tid < o) red[tid] = fmaxf(red[tid], red[tid + o]);
        __syncthreads();
    }
    float mx = red[0];
    __syncthreads();

    // pass 2: exp + sum
    float lsum = 0.f;
    for (int j = tid; j <= s; j += 128) {
        float e = __expf(pr[j] - mx);
        pr[j] = e;
        lsum += e;
    }
    red[tid] = lsum;
    __syncthreads();
    for (int o = 64; o > 0; o >>= 1) {
        if (tid < o) red[tid] += red[tid + o];
        __syncthreads();
    }
    float inv = 1.0f / red[0];
    __syncthreads();

    // pass 3: ctx[d] = sum_j p[j] * v[j][d]; two groups split over j parity
    const int ggrp = tid >> 6;   // 0 or 1
    const int d    = tid & 63;
    float acc = 0.f;
    for (int j = ggrp; j <= s; j += 2)
        acc += pr[j] * v[(b * SS + j) * DD + h * DK + d];
    red[tid] = acc;
    __syncthreads();
    if (ggrp == 0)
        g_ctx[(b * SS + s) * DD + h * DK + d] = (red[d] + red[64 + d]) * inv;
}

// ---------------- driver ---------------------------------------------------
extern "C" void kernel_launch(void* const* d_in, const int* in_sizes, int n_in,
                              void* d_out, int out_size) {
    (void)in_sizes; (void)n_in; (void)out_size;
    const float* tok  = (const float*)d_in[1];
    const float* pos  = (const float*)d_in[2];
    const float* Wq   = (const float*)d_in[3];
    const float* bq   = (const float*)d_in[4];
    const float* Wk   = (const float*)d_in[5];
    const float* bk   = (const float*)d_in[6];
    const float* Wv   = (const float*)d_in[7];
    const float* bv   = (const float*)d_in[8];
    const float* Wo   = (const float*)d_in[9];
    const float* bo   = (const float*)d_in[10];
    const float* W1   = (const float*)d_in[11];
    const float* b1   = (const float*)d_in[12];
    const float* W2   = (const float*)d_in[13];
    const float* b2   = (const float*)d_in[14];
    const float* ln1g = (const float*)d_in[15];
    const float* ln1b = (const float*)d_in[16];
    const float* ln2g = (const float*)d_in[17];
    const float* ln2b = (const float*)d_in[18];
    const float* lnfg = (const float*)d_in[19];
    const float* lnfb = (const float*)d_in[20];
    float* out = (float*)d_out;

    float *h, *y, *q, *k, *v, *ctx, *ffn;
    cudaGetSymbolAddress((void**)&h,   g_h);
    cudaGetSymbolAddress((void**)&y,   g_y);
    cudaGetSymbolAddress((void**)&q,   g_q);
    cudaGetSymbolAddress((void**)&k,   g_k);
    cudaGetSymbolAddress((void**)&v,   g_v);
    cudaGetSymbolAddress((void**)&ctx, g_ctx);
    cudaGetSymbolAddress((void**)&ffn, g_ffn);

    cvt_x_kernel<<<1, 256>>>((const long long*)d_in[0]);
    embed_kernel<<<(MTOK * DD + 255) / 256, 256>>>(tok, pos);

    dim3 gD(DD / 128, MTOK / 128);   // (6, 16)
    dim3 gF(FF / 128, MTOK / 128);   // (24, 16)
    dim3 gV(VV / 128, MTOK / 128);   // (250, 16)

    for (int l = 0; l < LL; l++) {
        ln_kernel<<<MTOK, 256>>>(h, ln1g + l * DD, ln1b + l * DD, y);
        sgemm_kernel<true, false, false><<<gD, 256>>>(y, Wq + l * DD * DD, bq + l * DD, nullptr, q,   MTOK, DD, DD);
        sgemm_kernel<true, false, false><<<gD, 256>>>(y, Wk + l * DD * DD, bk + l * DD, nullptr, k,   MTOK, DD, DD);
        sgemm_kernel<true, false, false><<<gD, 256>>>(y, Wv + l * DD * DD, bv + l * DD, nullptr, v,   MTOK, DD, DD);
        attn_kernel<<<dim3(SS, HH, BB), 128>>>(q, k, v);   // writes g_ctx
        sgemm_kernel<true, false, true ><<<gD, 256>>>(ctx, Wo + l * DD * DD, bo + l * DD, h, h,       MTOK, DD, DD);
        ln_kernel<<<MTOK, 256>>>(h, ln2g + l * DD, ln2b + l * DD, y);
        sgemm_kernel<true, true,  false><<<gF, 256>>>(y,   W1 + l * FF * DD, b1 + l * FF, nullptr, ffn, MTOK, FF, DD);
        sgemm_kernel<true, false, true ><<<gD, 256>>>(ffn, W2 + l * DD * FF, b2 + l * DD, h, h,       MTOK, DD, FF);
    }

    ln_kernel<<<MTOK, 256>>>(h, lnfg, lnfb, y);
    sgemm_kernel<false, false, false><<<gV, 256>>>(y, tok, nullptr, nullptr, out, MTOK, VV, DD);
}

// round 3
// speedup vs baseline: 1.7337x; 1.7337x over previous
#include <cuda_runtime.h>
#include <cuda_bf16.h>
#include <cstdint>
#include <math.h>

#define BB 2
#define SS 1024
#define DD 768
#define HH 12
#define DK 64
#define FF 3072
#define LL 4
#define VV 32000
#define MTOK (BB*SS)   /* 2048 */

// ---------------- fp32 scratch ---------------------------------------------
__device__ float g_h  [MTOK*DD];
__device__ float g_y  [MTOK*DD];
__device__ float g_q  [MTOK*DD];
__device__ float g_k  [MTOK*DD];
__device__ float g_v  [MTOK*DD];
__device__ float g_ctx[MTOK*DD];
__device__ float g_ffn[MTOK*FF];
__device__ int   g_xi [MTOK];

// ---------------- bf16 split scratch ---------------------------------------
__device__ __nv_bfloat16 g_tok_hi[VV*DD],    g_tok_lo[VV*DD];
__device__ __nv_bfloat16 g_wq_hi [LL*DD*DD], g_wq_lo [LL*DD*DD];
__device__ __nv_bfloat16 g_wk_hi [LL*DD*DD], g_wk_lo [LL*DD*DD];
__device__ __nv_bfloat16 g_wv_hi [LL*DD*DD], g_wv_lo [LL*DD*DD];
__device__ __nv_bfloat16 g_wo_hi [LL*DD*DD], g_wo_lo [LL*DD*DD];
__device__ __nv_bfloat16 g_w1_hi [LL*FF*DD], g_w1_lo [LL*FF*DD];
__device__ __nv_bfloat16 g_w2_hi [LL*DD*FF], g_w2_lo [LL*DD*FF];
__device__ __nv_bfloat16 g_act_hi[MTOK*FF],  g_act_lo[MTOK*FF];

// ---------------- helpers ---------------------------------------------------
__device__ __forceinline__ uint32_t smem_u32(const void* p) {
    uint32_t a;
    asm("{ .reg .u64 t; cvta.to.shared.u64 t, %1; cvt.u32.u64 %0, t; }" : "=r"(a) : "l"(p));
    return a;
}
__device__ __forceinline__ void cpasync16(uint32_t saddr, const void* gaddr) {
    asm volatile("cp.async.cg.shared.global [%0], [%1], 16;" :: "r"(saddr), "l"(gaddr));
}
#define CP_COMMIT() asm volatile("cp.async.commit_group;" ::: "memory")
#define CP_WAIT(N)  asm volatile("cp.async.wait_group %0;" :: "n"(N) : "memory")

__device__ __forceinline__ void ldsm4(uint32_t* r, uint32_t addr) {
    asm volatile("ldmatrix.sync.aligned.m8n8.x4.shared.b16 {%0,%1,%2,%3}, [%4];"
        : "=r"(r[0]), "=r"(r[1]), "=r"(r[2]), "=r"(r[3]) : "r"(addr));
}
__device__ __forceinline__ void mma16816(float* c, const uint32_t* a, const uint32_t* b) {
    asm volatile(
        "mma.sync.aligned.m16n8k16.row.col.f32.bf16.bf16.f32 "
        "{%0,%1,%2,%3}, {%4,%5,%6,%7}, {%8,%9}, {%0,%1,%2,%3};"
        : "+f"(c[0]), "+f"(c[1]), "+f"(c[2]), "+f"(c[3])
        : "r"(a[0]), "r"(a[1]), "r"(a[2]), "r"(a[3]), "r"(b[0]), "r"(b[1]));
}

// ---------------- token ids / embed / layernorm -----------------------------
__global__ void cvt_x_kernel(const long long* __restrict__ x64) {
    __shared__ int is64;
    if (threadIdx.x == 0) {
        int ok = 1;
        for (int i = 0; i < 16; i++) { long long t = x64[i]; if (t < 0 || t >= VV) ok = 0; }
        is64 = ok;
    }
    __syncthreads();
    const int* x32 = (const int*)x64;
    if (is64) for (int i = threadIdx.x; i < MTOK; i += blockDim.x) g_xi[i] = (int)x64[i];
    else      for (int i = threadIdx.x; i < MTOK; i += blockDim.x) g_xi[i] = x32[i];
}

__global__ void embed_kernel(const float* __restrict__ tok, const float* __restrict__ pos) {
    int idx = blockIdx.x * blockDim.x + threadIdx.x;
    if (idx < MTOK * DD) {
        int d = idx % DD, t = idx / DD, s = t % SS;
        g_h[idx] = tok[g_xi[t] * DD + d] + pos[s * DD + d];
    }
}

__global__ void ln_kernel(const float* __restrict__ in, const float* __restrict__ g,
                          const float* __restrict__ b, float* __restrict__ out) {
    int row = blockIdx.x, tid = threadIdx.x;
    const float* xr = in + row * DD;
    __shared__ float r1[256], r2[256];
    float s1 = 0.f, s2 = 0.f;
    for (int i = tid; i < DD; i += 256) { float v = xr[i]; s1 += v; s2 += v * v; }
    r1[tid] = s1; r2[tid] = s2;
    __syncthreads();
    for (int o = 128; o > 0; o >>= 1) {
        if (tid < o) { r1[tid] += r1[tid + o]; r2[tid] += r2[tid + o]; }
        __syncthreads();
    }
    float mu = r1[0] * (1.0f / DD);
    float var = r2[0] * (1.0f / DD) - mu * mu;
    float inv = rsqrtf(var + 1e-5f);
    for (int i = tid; i < DD; i += 256)
        out[row * DD + i] = (xr[i] - mu) * inv * g[i] + b[i];
}

// ---------------- fp32 -> bf16 hi/lo split ----------------------------------
__global__ void split_kernel(const float4* __restrict__ x,
                             __nv_bfloat162* __restrict__ hi,
                             __nv_bfloat162* __restrict__ lo, int n4) {
    int i = blockIdx.x * blockDim.x + threadIdx.x;
    if (i < n4) {
        float4 v = x[i];
        __nv_bfloat16 hx = __float2bfloat16(v.x), hy = __float2bfloat16(v.y);
        __nv_bfloat16 hz = __float2bfloat16(v.z), hw = __float2bfloat16(v.w);
        float lx = v.x - __bfloat162float(hx), ly = v.y - __bfloat162float(hy);
        float lz = v.z - __bfloat162float(hz), lw = v.w - __bfloat162float(hw);
        hi[2*i]   = __nv_bfloat162(hx, hy);
        hi[2*i+1] = __nv_bfloat162(hz, hw);
        lo[2*i]   = __nv_bfloat162(__float2bfloat16(lx), __float2bfloat16(ly));
        lo[2*i+1] = __nv_bfloat162(__float2bfloat16(lz), __float2bfloat16(lw));
    }
}

// ---------------- split-bf16 mma.sync GEMM ----------------------------------
// C[M,N] = A[M,K]*B[N,K]^T via Ahi*Bhi + Ahi*Blo + Alo*Bhi (fp32 accum).
// CTA tile 128x128, 8 warps of 64x32. K staged by 32, cp.async double buffer.
// SMEM rows padded to 40 bf16 (80B) -> conflict-free ldmatrix.
#define PADE   40
#define TILEB  (128*PADE*2)          /* 10240 B per tile */
#define STAGEB (4*TILEB)             /* Ahi|Alo|Bhi|Blo  */
#define GSMEM  (2*STAGEB)            /* 81920 B          */

__device__ __forceinline__ void load_stage(
        uint32_t sbase, int tid,
        const __nv_bfloat16* Ahi, const __nv_bfloat16* Alo,
        const __nv_bfloat16* Bhi, const __nv_bfloat16* Blo,
        int m0, int n0, int k0, int K) {
    const int c = tid & 3;           // 16B chunk within row (4 per 64B row)
    const int r = tid >> 2;          // 0..63
    const __nv_bfloat16* srcs[4] = { Ahi, Alo, Bhi, Blo };
    const int rows0[4] = { m0, m0, n0, n0 };
#pragma unroll
    for (int t = 0; t < 4; t++) {
        uint32_t tb = sbase + t * TILEB;
        const __nv_bfloat16* s = srcs[t];
#pragma unroll
        for (int hrow = 0; hrow < 2; hrow++) {
            int row = r + hrow * 64;
            cpasync16(tb + row * (PADE * 2) + c * 16,
                      s + (size_t)(rows0[t] + row) * K + k0 + c * 8);
        }
    }
}

template<bool HASBIAS, bool RELU, bool RES>
__global__ __launch_bounds__(256, 2)
void mm_gemm(const __nv_bfloat16* __restrict__ Ahi, const __nv_bfloat16* __restrict__ Alo,
             const __nv_bfloat16* __restrict__ Bhi, const __nv_bfloat16* __restrict__ Blo,
             const float* __restrict__ bias, const float* __restrict__ res,
             float* __restrict__ C, int M, int N, int K) {
    extern __shared__ char smem_raw[];
    const uint32_t sb = smem_u32(smem_raw);
    const int tid = threadIdx.x;
    const int wid = tid >> 5, lane = tid & 31;
    const int m0 = blockIdx.y * 128, n0 = blockIdx.x * 128;
    const int wm = (wid >> 2) * 64;          // warp m offset in tile
    const int wn = (wid & 3) * 32;           // warp n offset in tile

    float Cf[4][4][4];
#pragma unroll
    for (int i = 0; i < 4; i++)
#pragma unroll
        for (int j = 0; j < 4; j++)
#pragma unroll
            for (int x = 0; x < 4; x++) Cf[i][j][x] = 0.f;

    const int NS = K >> 5;

    // ldmatrix per-thread address offsets (within a tile, padded stride)
    const int a_row = (lane & 15);
    const int a_colsel = (lane >> 4) * 8;            // 0 or 8
    const int b_row = (lane & 7) + ((lane >> 4) & 1) * 8;
    const int b_colsel = ((lane >> 3) & 1) * 8;      // 0 or 8

    load_stage(sb, tid, Ahi, Alo, Bhi, Blo, m0, n0, 0, K);
    CP_COMMIT();

    for (int s = 0; s < NS; s++) {
        if (s + 1 < NS) {
            load_stage(sb + ((s + 1) & 1) * STAGEB, tid, Ahi, Alo, Bhi, Blo,
                       m0, n0, (s + 1) << 5, K);
            CP_COMMIT();
            CP_WAIT(1);
        } else {
            CP_WAIT(0);
        }
        __syncthreads();

        const uint32_t st = sb + (s & 1) * STAGEB;
        const uint32_t tAh = st;
        const uint32_t tAl = st + TILEB;
        const uint32_t tBh = st + 2 * TILEB;
        const uint32_t tBl = st + 3 * TILEB;

#pragma unroll
        for (int k16 = 0; k16 < 32; k16 += 16) {
            uint32_t Af[4][4], Bf[2][4];
            // pass 1: Ahi * Bhi
#pragma unroll
            for (int mf = 0; mf < 4; mf++)
                ldsm4(Af[mf], tAh + (wm + mf * 16 + a_row) * (PADE * 2) + (k16 + a_colsel) * 2);
#pragma unroll
            for (int p = 0; p < 2; p++)
                ldsm4(Bf[p], tBh + (wn + p * 16 + b_row) * (PADE * 2) + (k16 + b_colsel) * 2);
#pragma unroll
            for (int mf = 0; mf < 4; mf++)
#pragma unroll
                for (int nf = 0; nf < 4; nf++)
                    mma16816(Cf[mf][nf], Af[mf], &Bf[nf >> 1][(nf & 1) * 2]);
            // pass 2: Ahi * Blo
#pragma unroll
            for (int p = 0; p < 2; p++)
                ldsm4(Bf[p], tBl + (wn + p * 16 + b_row) * (PADE * 2) + (k16 + b_colsel) * 2);
#pragma unroll
            for (int mf = 0; mf < 4; mf++)
#pragma unroll
                for (int nf = 0; nf < 4; nf++)
                    mma16816(Cf[mf][nf], Af[mf], &Bf[nf >> 1][(nf & 1) * 2]);
            // pass 3: Alo * Bhi
#pragma unroll
            for (int mf = 0; mf < 4; mf++)
                ldsm4(Af[mf], tAl + (wm + mf * 16 + a_row) * (PADE * 2) + (k16 + a_colsel) * 2);
#pragma unroll
            for (int p = 0; p < 2; p++)
                ldsm4(Bf[p], tBh + (wn + p * 16 + b_row) * (PADE * 2) + (k16 + b_colsel) * 2);
#pragma unroll
            for (int mf = 0; mf < 4; mf++)
#pragma unroll
                for (int nf = 0; nf < 4; nf++)
                    mma16816(Cf[mf][nf], Af[mf], &Bf[nf >> 1][(nf & 1) * 2]);
        }
        __syncthreads();
    }

    // epilogue: mma C frag layout -> global
    const int g = lane >> 2, t2 = (lane & 3) * 2;
#pragma unroll
    for (int mf = 0; mf < 4; mf++) {
#pragma unroll
        for (int nf = 0; nf < 4; nf++) {
            int n = n0 + wn + nf * 8 + t2;
#pragma unroll
            for (int hrow = 0; hrow < 2; hrow++) {
                int m = m0 + wm + mf * 16 + g + hrow * 8;
                float v0 = Cf[mf][nf][hrow * 2 + 0];
                float v1 = Cf[mf][nf][hrow * 2 + 1];
                if (HASBIAS) { v0 += bias[n]; v1 += bias[n + 1]; }
                if (RELU)    { v0 = fmaxf(v0, 0.f); v1 = fmaxf(v1, 0.f); }
                if (RES) {
                    const float2 rr = *(const float2*)&res[(size_t)m * N + n];
                    v0 += rr.x; v1 += rr.y;
                }
                *(float2*)&C[(size_t)m * N + n] = make_float2(v0, v1);
            }
        }
    }
}

// ---------------- causal attention (fp32) -----------------------------------
__global__ void attn_kernel(const float* __restrict__ q, const float* __restrict__ k,
                            const float* __restrict__ v) {
    const int s = blockIdx.x, h = blockIdx.y, b = blockIdx.z;
    const int tid = threadIdx.x;
    __shared__ float qs[DK];
    __shared__ float pr[SS];
    __shared__ float red[128];

    const float* qrow = q + ((b * SS + s) * DD + h * DK);
    if (tid < DK) qs[tid] = qrow[tid];
    __syncthreads();

    float lmax = -1e30f;
    for (int j = tid; j <= s; j += 128) {
        const float4* kr4 = (const float4*)(k + ((b * SS + j) * DD + h * DK));
        float dot = 0.f;
#pragma unroll
        for (int d4 = 0; d4 < 16; d4++) {
            float4 kk4 = kr4[d4];
            dot += qs[d4*4+0]*kk4.x + qs[d4*4+1]*kk4.y + qs[d4*4+2]*kk4.z + qs[d4*4+3]*kk4.w;
        }
        dot *= 0.125f;
        pr[j] = dot;
        lmax = fmaxf(lmax, dot);
    }
    red[tid] = lmax; __syncthreads();
    for (int o = 64; o > 0; o >>= 1) { if (tid < o) red[tid] = fmaxf(red[tid], red[tid+o]); __syncthreads(); }
    float mx = red[0]; __syncthreads();

    float lsum = 0.f;
    for (int j = tid; j <= s; j += 128) { float e = __expf(pr[j] - mx); pr[j] = e; lsum += e; }
    red[tid] = lsum; __syncthreads();
    for (int o = 64; o > 0; o >>= 1) { if (tid < o) red[tid] += red[tid+o]; __syncthreads(); }
    float inv = 1.0f / red[0]; __syncthreads();

    const int ggrp = tid >> 6, d = tid & 63;
    float acc = 0.f;
    for (int j = ggrp; j <= s; j += 2)
        acc += pr[j] * v[(b * SS + j) * DD + h * DK + d];
    red[tid] = acc; __syncthreads();
    if (ggrp == 0)
        g_ctx[(b * SS + s) * DD + h * DK + d] = (red[d] + red[64 + d]) * inv;
}

// ---------------- driver ----------------------------------------------------
typedef __nv_bfloat16 bf16;

static void split_launch(const float* x, bf16* hi, bf16* lo, long long n) {
    int n4 = (int)(n / 4);
    split_kernel<<<(n4 + 255) / 256, 256>>>((const float4*)x, (__nv_bfloat162*)hi, (__nv_bfloat162*)lo, n4);
}

extern "C" void kernel_launch(void* const* d_in, const int* in_sizes, int n_in,
                              void* d_out, int out_size) {
    (void)in_sizes; (void)n_in; (void)out_size;
    const float* tok  = (const float*)d_in[1];
    const float* pos  = (const float*)d_in[2];
    const float* bq   = (const float*)d_in[4];
    const float* bk   = (const float*)d_in[6];
    const float* bv   = (const float*)d_in[8];
    const float* bo   = (const float*)d_in[10];
    const float* b1   = (const float*)d_in[12];
    const float* b2   = (const float*)d_in[14];
    const float* ln1g = (const float*)d_in[15];
    const float* ln1b = (const float*)d_in[16];
    const float* ln2g = (const float*)d_in[17];
    const float* ln2b = (const float*)d_in[18];
    const float* lnfg = (const float*)d_in[19];
    const float* lnfb = (const float*)d_in[20];
    float* out = (float*)d_out;

    float *h, *y, *q, *k, *v, *ctx, *ffn;
    cudaGetSymbolAddress((void**)&h,   g_h);
    cudaGetSymbolAddress((void**)&y,   g_y);
    cudaGetSymbolAddress((void**)&q,   g_q);
    cudaGetSymbolAddress((void**)&k,   g_k);
    cudaGetSymbolAddress((void**)&v,   g_v);
    cudaGetSymbolAddress((void**)&ctx, g_ctx);
    cudaGetSymbolAddress((void**)&ffn, g_ffn);

    bf16 *tokh, *tokl, *wqh, *wql, *wkh, *wkl, *wvh, *wvl, *woh, *wol;
    bf16 *w1h, *w1l, *w2h, *w2l, *ah, *al;
    cudaGetSymbolAddress((void**)&tokh, g_tok_hi); cudaGetSymbolAddress((void**)&tokl, g_tok_lo);
    cudaGetSymbolAddress((void**)&wqh,  g_wq_hi);  cudaGetSymbolAddress((void**)&wql,  g_wq_lo);
    cudaGetSymbolAddress((void**)&wkh,  g_wk_hi);  cudaGetSymbolAddress((void**)&wkl,  g_wk_lo);
    cudaGetSymbolAddress((void**)&wvh,  g_wv_hi);  cudaGetSymbolAddress((void**)&wvl,  g_wv_lo);
    cudaGetSymbolAddress((void**)&woh,  g_wo_hi);  cudaGetSymbolAddress((void**)&wol,  g_wo_lo);
    cudaGetSymbolAddress((void**)&w1h,  g_w1_hi);  cudaGetSymbolAddress((void**)&w1l,  g_w1_lo);
    cudaGetSymbolAddress((void**)&w2h,  g_w2_hi);  cudaGetSymbolAddress((void**)&w2l,  g_w2_lo);
    cudaGetSymbolAddress((void**)&ah,   g_act_hi); cudaGetSymbolAddress((void**)&al,   g_act_lo);

    cudaFuncSetAttribute(mm_gemm<true,  false, false>, cudaFuncAttributeMaxDynamicSharedMemorySize, GSMEM);
    cudaFuncSetAttribute(mm_gemm<true,  false, true >, cudaFuncAttributeMaxDynamicSharedMemorySize, GSMEM);
    cudaFuncSetAttribute(mm_gemm<true,  true,  false>, cudaFuncAttributeMaxDynamicSharedMemorySize, GSMEM);
    cudaFuncSetAttribute(mm_gemm<false, false, false>, cudaFuncAttributeMaxDynamicSharedMemorySize, GSMEM);

    // weight splits (once per call; graph replays them, still cheap)
    split_launch(tok,                   tokh, tokl, (long long)VV * DD);
    split_launch((const float*)d_in[3],  wqh, wql, (long long)LL * DD * DD);
    split_launch((const float*)d_in[5],  wkh, wkl, (long long)LL * DD * DD);
    split_launch((const float*)d_in[7],  wvh, wvl, (long long)LL * DD * DD);
    split_launch((const float*)d_in[9],  woh, wol, (long long)LL * DD * DD);
    split_launch((const float*)d_in[11], w1h, w1l, (long long)LL * FF * DD);
    split_launch((const float*)d_in[13], w2h, w2l, (long long)LL * DD * FF);

    cvt_x_kernel<<<1, 256>>>((const long long*)d_in[0]);
    embed_kernel<<<(MTOK * DD + 255) / 256, 256>>>(tok, pos);

    dim3 gD(DD / 128, MTOK / 128);   // (6, 16)
    dim3 gF(FF / 128, MTOK / 128);   // (24, 16)
    dim3 gV(VV / 128, MTOK / 128);   // (250, 16)

    for (int l = 0; l < LL; l++) {
        ln_kernel<<<MTOK, 256>>>(h, ln1g + l * DD, ln1b + l * DD, y);
        split_launch(y, ah, al, (long long)MTOK * DD);
        mm_gemm<true, false, false><<<gD, 256, GSMEM>>>(ah, al, wqh + (size_t)l*DD*DD, wql + (size_t)l*DD*DD, bq + l*DD, nullptr, q, MTOK, DD, DD);
        mm_gemm<true, false, false><<<gD, 256, GSMEM>>>(ah, al, wkh + (size_t)l*DD*DD, wkl + (size_t)l*DD*DD, bk + l*DD, nullptr, k, MTOK, DD, DD);
        mm_gemm<true, false, false><<<gD, 256, GSMEM>>>(ah, al, wvh + (size_t)l*DD*DD, wvl + (size_t)l*DD*DD, bv + l*DD, nullptr, v, MTOK, DD, DD);
        attn_kernel<<<dim3(SS, HH, BB), 128>>>(q, k, v);   // writes g_ctx
        split_launch(ctx, ah, al, (long long)MTOK * DD);
        mm_gemm<true, false, true ><<<gD, 256, GSMEM>>>(ah, al, woh + (size_t)l*DD*DD, wol + (size_t)l*DD*DD, bo + l*DD, h, h, MTOK, DD, DD);
        ln_kernel<<<MTOK, 256>>>(h, ln2g + l * DD, ln2b + l * DD, y);
        split_launch(y, ah, al, (long long)MTOK * DD);
        mm_gemm<true, true,  false><<<gF, 256, GSMEM>>>(ah, al, w1h + (size_t)l*FF*DD, w1l + (size_t)l*FF*DD, b1 + l*FF, nullptr, ffn, MTOK, FF, DD);
        split_launch(ffn, ah, al, (long long)MTOK * FF);
        mm_gemm<true, false, true ><<<gD, 256, GSMEM>>>(ah, al, w2h + (size_t)l*DD*FF, w2l + (size_t)l*DD*FF, b2 + l*DD, h, h, MTOK, DD, FF);
    }

    ln_kernel<<<MTOK, 256>>>(h, lnfg, lnfb, y);
    split_launch(y, ah, al, (long long)MTOK * DD);
    mm_gemm<false, false, false><<<gV, 256, GSMEM>>>(ah, al, tokh, tokl, nullptr, nullptr, out, MTOK, VV, DD);
}

// round 4
// speedup vs baseline: 3.5843x; 2.0674x over previous
#include <cuda_runtime.h>
#include <cuda_bf16.h>
#include <cstdint>
#include <math.h>

#define BB 2
#define SS 1024
#define DD 768
#define HH 12
#define DK 64
#define FF 3072
#define LL 4
#define VV 32000
#define MTOK (BB*SS)   /* 2048 */

typedef __nv_bfloat16 bf16;

// ---------------- fp32 scratch ---------------------------------------------
__device__ float g_h  [MTOK*DD];
__device__ float g_q  [MTOK*DD];
__device__ float g_k  [MTOK*DD];
__device__ float g_v  [MTOK*DD];
__device__ int   g_xi [MTOK];

// ---------------- bf16 split scratch ---------------------------------------
__device__ bf16 g_tok_hi[VV*DD],    g_tok_lo[VV*DD];
__device__ bf16 g_wq_hi [LL*DD*DD], g_wq_lo [LL*DD*DD];
__device__ bf16 g_wk_hi [LL*DD*DD], g_wk_lo [LL*DD*DD];
__device__ bf16 g_wv_hi [LL*DD*DD], g_wv_lo [LL*DD*DD];
__device__ bf16 g_wo_hi [LL*DD*DD], g_wo_lo [LL*DD*DD];
__device__ bf16 g_w1_hi [LL*FF*DD], g_w1_lo [LL*FF*DD];
__device__ bf16 g_w2_hi [LL*DD*FF], g_w2_lo [LL*DD*FF];
__device__ bf16 g_a_hi  [MTOK*DD],  g_a_lo  [MTOK*DD];   // ln / attn-ctx outputs
__device__ bf16 g_f_hi  [MTOK*FF],  g_f_lo  [MTOK*FF];   // relu(ffn) output

// ---------------- helpers ---------------------------------------------------
__device__ __forceinline__ uint32_t smem_u32(const void* p) {
    uint32_t a;
    asm("{ .reg .u64 t; cvta.to.shared.u64 t, %1; cvt.u32.u64 %0, t; }" : "=r"(a) : "l"(p));
    return a;
}
__device__ __forceinline__ void cpasync16(uint32_t saddr, const void* gaddr) {
    asm volatile("cp.async.cg.shared.global [%0], [%1], 16;" :: "r"(saddr), "l"(gaddr));
}
#define CP_COMMIT() asm volatile("cp.async.commit_group;" ::: "memory")
#define CP_WAIT(N)  asm volatile("cp.async.wait_group %0;" :: "n"(N) : "memory")

__device__ __forceinline__ void ldsm4(uint32_t* r, uint32_t addr) {
    asm volatile("ldmatrix.sync.aligned.m8n8.x4.shared.b16 {%0,%1,%2,%3}, [%4];"
        : "=r"(r[0]), "=r"(r[1]), "=r"(r[2]), "=r"(r[3]) : "r"(addr));
}
__device__ __forceinline__ void mma16816(float* c, const uint32_t* a, const uint32_t* b) {
    asm volatile(
        "mma.sync.aligned.m16n8k16.row.col.f32.bf16.bf16.f32 "
        "{%0,%1,%2,%3}, {%4,%5,%6,%7}, {%8,%9}, {%0,%1,%2,%3};"
        : "+f"(c[0]), "+f"(c[1]), "+f"(c[2]), "+f"(c[3])
        : "r"(a[0]), "r"(a[1]), "r"(a[2]), "r"(a[3]), "r"(b[0]), "r"(b[1]));
}
__device__ __forceinline__ void split1(float v, bf16& h, bf16& l) {
    h = __float2bfloat16(v);
    l = __float2bfloat16(v - __bfloat162float(h));
}

// ---------------- token ids / embed ----------------------------------------
__global__ void cvt_x_kernel(const long long* __restrict__ x64) {
    __shared__ int is64;
    if (threadIdx.x == 0) {
        int ok = 1;
        for (int i = 0; i < 16; i++) { long long t = x64[i]; if (t < 0 || t >= VV) ok = 0; }
        is64 = ok;
    }
    __syncthreads();
    const int* x32 = (const int*)x64;
    if (is64) for (int i = threadIdx.x; i < MTOK; i += blockDim.x) g_xi[i] = (int)x64[i];
    else      for (int i = threadIdx.x; i < MTOK; i += blockDim.x) g_xi[i] = x32[i];
}

__global__ void embed_kernel(const float* __restrict__ tok, const float* __restrict__ pos) {
    int idx = blockIdx.x * blockDim.x + threadIdx.x;
    if (idx < MTOK * DD) {
        int d = idx % DD, t = idx / DD, s = t % SS;
        g_h[idx] = tok[g_xi[t] * DD + d] + pos[s * DD + d];
    }
}

// ---------------- layernorm -> bf16 hi/lo ----------------------------------
__global__ void ln_kernel(const float* __restrict__ in, const float* __restrict__ g,
                          const float* __restrict__ b,
                          bf16* __restrict__ ohi, bf16* __restrict__ olo) {
    int row = blockIdx.x, tid = threadIdx.x;
    const float* xr = in + (size_t)row * DD;
    __shared__ float r1[256], r2[256];
    float s1 = 0.f, s2 = 0.f;
    for (int i = tid; i < DD; i += 256) { float v = xr[i]; s1 += v; s2 += v * v; }
    r1[tid] = s1; r2[tid] = s2;
    __syncthreads();
    for (int o = 128; o > 0; o >>= 1) {
        if (tid < o) { r1[tid] += r1[tid + o]; r2[tid] += r2[tid + o]; }
        __syncthreads();
    }
    float mu = r1[0] * (1.0f / DD);
    float var = r2[0] * (1.0f / DD) - mu * mu;
    float inv = rsqrtf(var + 1e-5f);
    for (int i = tid; i < DD; i += 256) {
        float v = (xr[i] - mu) * inv * g[i] + b[i];
        bf16 h, l; split1(v, h, l);
        ohi[(size_t)row * DD + i] = h;
        olo[(size_t)row * DD + i] = l;
    }
}

// ---------------- fp32 -> bf16 hi/lo split (weights only) -------------------
__global__ void split_kernel(const float4* __restrict__ x,
                             __nv_bfloat162* __restrict__ hi,
                             __nv_bfloat162* __restrict__ lo, int n4) {
    int i = blockIdx.x * blockDim.x + threadIdx.x;
    if (i < n4) {
        float4 v = x[i];
        bf16 hx, lx, hy, ly, hz, lz, hw, lw;
        split1(v.x, hx, lx); split1(v.y, hy, ly);
        split1(v.z, hz, lz); split1(v.w, hw, lw);
        hi[2*i]   = __nv_bfloat162(hx, hy);
        hi[2*i+1] = __nv_bfloat162(hz, hw);
        lo[2*i]   = __nv_bfloat162(lx, ly);
        lo[2*i+1] = __nv_bfloat162(lz, lw);
    }
}

// ---------------- split-bf16 mma.sync GEMM core -----------------------------
// C[M,N] = A[M,K]*B[N,K]^T via Ahi*Bhi + Ahi*Blo + Alo*Bhi (fp32 accum).
// CTA tile 128x128, 8 warps of 64x32, K staged by 32, cp.async double buffer.
#define PADE   40
#define TILEB  (128*PADE*2)
#define STAGEB (4*TILEB)
#define GSMEM  (2*STAGEB)            /* 81920 B */

__device__ __forceinline__ void load_stage(
        uint32_t sbase, int tid,
        const bf16* Ahi, const bf16* Alo, const bf16* Bhi, const bf16* Blo,
        int m0, int n0, int k0, int K) {
    const int c = tid & 3;
    const int r = tid >> 2;
    const bf16* srcs[4] = { Ahi, Alo, Bhi, Blo };
    const int rows0[4] = { m0, m0, n0, n0 };
#pragma unroll
    for (int t = 0; t < 4; t++) {
        uint32_t tb = sbase + t * TILEB;
        const bf16* s = srcs[t];
#pragma unroll
        for (int hrow = 0; hrow < 2; hrow++) {
            int row = r + hrow * 64;
            cpasync16(tb + row * (PADE * 2) + c * 16,
                      s + (size_t)(rows0[t] + row) * K + k0 + c * 8);
        }
    }
}

// EPI: 0 = f32+bias, 1 = f32+bias+res, 2 = bf16split+bias+relu, 3 = f32
template<int EPI>
__device__ __forceinline__ void gemm_core(
        const bf16* Ahi, const bf16* Alo, const bf16* Bhi, const bf16* Blo,
        const float* bias, const float* res, float* C, bf16* Chi, bf16* Clo,
        int m0, int n0, int N, int K, uint32_t sb) {
    const int tid = threadIdx.x;
    const int wid = tid >> 5, lane = tid & 31;
    const int wm = (wid >> 2) * 64;
    const int wn = (wid & 3) * 32;

    float Cf[4][4][4];
#pragma unroll
    for (int i = 0; i < 4; i++)
#pragma unroll
        for (int j = 0; j < 4; j++)
#pragma unroll
            for (int x = 0; x < 4; x++) Cf[i][j][x] = 0.f;

    const int NS = K >> 5;
    const int a_row = (lane & 15);
    const int a_colsel = (lane >> 4) * 8;
    const int b_row = (lane & 7) + ((lane >> 4) & 1) * 8;
    const int b_colsel = ((lane >> 3) & 1) * 8;

    load_stage(sb, tid, Ahi, Alo, Bhi, Blo, m0, n0, 0, K);
    CP_COMMIT();

    for (int s = 0; s < NS; s++) {
        if (s + 1 < NS) {
            load_stage(sb + ((s + 1) & 1) * STAGEB, tid, Ahi, Alo, Bhi, Blo,
                       m0, n0, (s + 1) << 5, K);
            CP_COMMIT();
            CP_WAIT(1);
        } else {
            CP_WAIT(0);
        }
        __syncthreads();

        const uint32_t st = sb + (s & 1) * STAGEB;
        const uint32_t tAh = st;
        const uint32_t tAl = st + TILEB;
        const uint32_t tBh = st + 2 * TILEB;
        const uint32_t tBl = st + 3 * TILEB;

#pragma unroll
        for (int k16 = 0; k16 < 32; k16 += 16) {
            uint32_t Af[4][4], Bf[2][4];
#pragma unroll
            for (int mf = 0; mf < 4; mf++)
                ldsm4(Af[mf], tAh + (wm + mf * 16 + a_row) * (PADE * 2) + (k16 + a_colsel) * 2);
#pragma unroll
            for (int p = 0; p < 2; p++)
                ldsm4(Bf[p], tBh + (wn + p * 16 + b_row) * (PADE * 2) + (k16 + b_colsel) * 2);
#pragma unroll
            for (int mf = 0; mf < 4; mf++)
#pragma unroll
                for (int nf = 0; nf < 4; nf++)
                    mma16816(Cf[mf][nf], Af[mf], &Bf[nf >> 1][(nf & 1) * 2]);
#pragma unroll
            for (int p = 0; p < 2; p++)
                ldsm4(Bf[p], tBl + (wn + p * 16 + b_row) * (PADE * 2) + (k16 + b_colsel) * 2);
#pragma unroll
            for (int mf = 0; mf < 4; mf++)
#pragma unroll
                for (int nf = 0; nf < 4; nf++)
                    mma16816(Cf[mf][nf], Af[mf], &Bf[nf >> 1][(nf & 1) * 2]);
#pragma unroll
            for (int mf = 0; mf < 4; mf++)
                ldsm4(Af[mf], tAl + (wm + mf * 16 + a_row) * (PADE * 2) + (k16 + a_colsel) * 2);
#pragma unroll
            for (int p = 0; p < 2; p++)
                ldsm4(Bf[p], tBh + (wn + p * 16 + b_row) * (PADE * 2) + (k16 + b_colsel) * 2);
#pragma unroll
            for (int mf = 0; mf < 4; mf++)
#pragma unroll
                for (int nf = 0; nf < 4; nf++)
                    mma16816(Cf[mf][nf], Af[mf], &Bf[nf >> 1][(nf & 1) * 2]);
        }
        __syncthreads();
    }

    const int g = lane >> 2, t2 = (lane & 3) * 2;
#pragma unroll
    for (int mf = 0; mf < 4; mf++) {
#pragma unroll
        for (int nf = 0; nf < 4; nf++) {
            int n = n0 + wn + nf * 8 + t2;
#pragma unroll
            for (int hrow = 0; hrow < 2; hrow++) {
                int m = m0 + wm + mf * 16 + g + hrow * 8;
                float v0 = Cf[mf][nf][hrow * 2 + 0];
                float v1 = Cf[mf][nf][hrow * 2 + 1];
                if (EPI != 3) { v0 += bias[n]; v1 += bias[n + 1]; }
                if (EPI == 2) {
                    v0 = fmaxf(v0, 0.f); v1 = fmaxf(v1, 0.f);
                    bf16 h0, l0, h1, l1;
                    split1(v0, h0, l0); split1(v1, h1, l1);
                    *(__nv_bfloat162*)&Chi[(size_t)m * N + n] = __nv_bfloat162(h0, h1);
                    *(__nv_bfloat162*)&Clo[(size_t)m * N + n] = __nv_bfloat162(l0, l1);
                } else {
                    if (EPI == 1) {
                        const float2 rr = *(const float2*)&res[(size_t)m * N + n];
                        v0 += rr.x; v1 += rr.y;
                    }
                    *(float2*)&C[(size_t)m * N + n] = make_float2(v0, v1);
                }
            }
        }
    }
}

template<int EPI>
__global__ __launch_bounds__(256, 2)
void mm_gemm(const bf16* __restrict__ Ahi, const bf16* __restrict__ Alo,
             const bf16* __restrict__ Bhi, const bf16* __restrict__ Blo,
             const float* __restrict__ bias, const float* __restrict__ res,
             float* __restrict__ C, bf16* __restrict__ Chi, bf16* __restrict__ Clo,
             int N, int K) {
    extern __shared__ char smem_raw[];
    gemm_core<EPI>(Ahi, Alo, Bhi, Blo, bias, res, C, Chi, Clo,
                   blockIdx.y * 128, blockIdx.x * 128, N, K, smem_u32(smem_raw));
}

// fused QKV: grid.x = 18 (which = x/6, n-tile = x%6)
__global__ __launch_bounds__(256, 2)
void qkv_gemm(const bf16* __restrict__ Ahi, const bf16* __restrict__ Alo,
              const bf16* __restrict__ wqh, const bf16* __restrict__ wql,
              const bf16* __restrict__ wkh, const bf16* __restrict__ wkl,
              const bf16* __restrict__ wvh, const bf16* __restrict__ wvl,
              const float* __restrict__ bq, const float* __restrict__ bk,
              const float* __restrict__ bv,
              float* __restrict__ q, float* __restrict__ k, float* __restrict__ v) {
    extern __shared__ char smem_raw[];
    const int which = blockIdx.x / 6, nb = blockIdx.x % 6;
    const bf16* Bh = (which == 0) ? wqh : (which == 1) ? wkh : wvh;
    const bf16* Bl = (which == 0) ? wql : (which == 1) ? wkl : wvl;
    const float* bias = (which == 0) ? bq : (which == 1) ? bk : bv;
    float* C = (which == 0) ? q : (which == 1) ? k : v;
    gemm_core<0>(Ahi, Alo, Bh, Bl, bias, nullptr, C, nullptr, nullptr,
                 blockIdx.y * 128, nb * 128, DD, DD, smem_u32(smem_raw));
}

// ---------------- flash attention (fp32, 64x64 tiles) -----------------------
#define APAD 68
#define ATT_SMEM (4*64*APAD*4)

__global__ __launch_bounds__(128)
void flash_attn(const float* __restrict__ q, const float* __restrict__ k,
                const float* __restrict__ v,
                bf16* __restrict__ chi, bf16* __restrict__ clo) {
    const int qt = blockIdx.x, h = blockIdx.y, b = blockIdx.z;
    extern __shared__ float sm[];
    float* Qs = sm;
    float* Ks = Qs + 64 * APAD;
    float* Vs = Ks + 64 * APAD;
    float* Ps = Vs + 64 * APAD;

    const int tid = threadIdx.x;
    const int tx = tid & 15, ty = tid >> 4;   // tx: 4 dims / 4 strided cols; ty: 8 rows

    const size_t qrow0 = (size_t)(b * SS + qt * 64);
    const float* qb = q + qrow0 * DD + h * DK;

    for (int i = tid; i < 64 * 16; i += 128) {
        int r = i >> 4, c = i & 15;
        *(float4*)&Qs[r * APAD + c * 4] = *(const float4*)&qb[(size_t)r * DD + c * 4];
    }

    float O[8][4];
    float mrun[8], lrun[8];
#pragma unroll
    for (int r = 0; r < 8; r++) {
        mrun[r] = -1e30f; lrun[r] = 0.f;
#pragma unroll
        for (int d = 0; d < 4; d++) O[r][d] = 0.f;
    }
    __syncthreads();

    for (int jt = 0; jt <= qt; jt++) {
        const float* kb = k + ((size_t)(b * SS + jt * 64)) * DD + h * DK;
        const float* vb = v + ((size_t)(b * SS + jt * 64)) * DD + h * DK;
        for (int i = tid; i < 64 * 16; i += 128) {
            int r = i >> 4, c = i & 15;
            *(float4*)&Ks[r * APAD + c * 4] = *(const float4*)&kb[(size_t)r * DD + c * 4];
            *(float4*)&Vs[r * APAD + c * 4] = *(const float4*)&vb[(size_t)r * DD + c * 4];
        }
        __syncthreads();

        // scores: rows ty*8+r, cols tx + 16*c (strided to avoid bank conflicts)
        float s[8][4];
#pragma unroll
        for (int r = 0; r < 8; r++)
#pragma unroll
            for (int c = 0; c < 4; c++) s[r][c] = 0.f;

        for (int kk = 0; kk < DK; kk += 4) {
            float4 kv[4], qv[8];
#pragma unroll
            for (int c = 0; c < 4; c++) kv[c] = *(float4*)&Ks[(tx + 16 * c) * APAD + kk];
#pragma unroll
            for (int r = 0; r < 8; r++) qv[r] = *(float4*)&Qs[(ty * 8 + r) * APAD + kk];
#pragma unroll
            for (int r = 0; r < 8; r++)
#pragma unroll
                for (int c = 0; c < 4; c++)
                    s[r][c] += qv[r].x * kv[c].x + qv[r].y * kv[c].y
                             + qv[r].z * kv[c].z + qv[r].w * kv[c].w;
        }

        const bool diag = (jt == qt);
#pragma unroll
        for (int r = 0; r < 8; r++) {
            const int qg = ty * 8 + r;
            float mt = -1e30f;
#pragma unroll
            for (int c = 0; c < 4; c++) {
                float sv = s[r][c] * 0.125f;
                if (diag && (tx + 16 * c) > qg) sv = -1e30f;
                s[r][c] = sv;
                mt = fmaxf(mt, sv);
            }
#pragma unroll
            for (int o = 8; o >= 1; o >>= 1)
                mt = fmaxf(mt, __shfl_xor_sync(0xffffffffu, mt, o, 16));
            float mn = fmaxf(mrun[r], mt);
            float f = __expf(mrun[r] - mn);
            mrun[r] = mn;
            float rs = 0.f;
#pragma unroll
            for (int c = 0; c < 4; c++) {
                float e = __expf(s[r][c] - mn);
                Ps[qg * APAD + tx + 16 * c] = e;
                rs += e;
            }
#pragma unroll
            for (int o = 8; o >= 1; o >>= 1)
                rs += __shfl_xor_sync(0xffffffffu, rs, o, 16);
            lrun[r] = lrun[r] * f + rs;
#pragma unroll
            for (int d = 0; d < 4; d++) O[r][d] *= f;
        }
        __syncthreads();

        // O += P @ V  (dims tx*4..+3)
        for (int j = 0; j < 64; j += 4) {
            float4 vv[4];
#pragma unroll
            for (int jj = 0; jj < 4; jj++)
                vv[jj] = *(float4*)&Vs[(j + jj) * APAD + tx * 4];
#pragma unroll
            for (int r = 0; r < 8; r++) {
                float4 pv = *(float4*)&Ps[(ty * 8 + r) * APAD + j];
                O[r][0] += pv.x * vv[0].x + pv.y * vv[1].x + pv.z * vv[2].x + pv.w * vv[3].x;
                O[r][1] += pv.x * vv[0].y + pv.y * vv[1].y + pv.z * vv[2].y + pv.w * vv[3].y;
                O[r][2] += pv.x * vv[0].z + pv.y * vv[1].z + pv.z * vv[2].z + pv.w * vv[3].z;
                O[r][3] += pv.x * vv[0].w + pv.y * vv[1].w + pv.z * vv[2].w + pv.w * vv[3].w;
            }
        }
        __syncthreads();
    }

#pragma unroll
    for (int r = 0; r < 8; r++) {
        float inv = 1.0f / lrun[r];
        size_t base = (qrow0 + ty * 8 + r) * DD + h * DK + tx * 4;
        bf16 h0, l0, h1, l1, h2, l2, h3, l3;
        split1(O[r][0] * inv, h0, l0); split1(O[r][1] * inv, h1, l1);
        split1(O[r][2] * inv, h2, l2); split1(O[r][3] * inv, h3, l3);
        *(__nv_bfloat162*)&chi[base]     = __nv_bfloat162(h0, h1);
        *(__nv_bfloat162*)&chi[base + 2] = __nv_bfloat162(h2, h3);
        *(__nv_bfloat162*)&clo[base]     = __nv_bfloat162(l0, l1);
        *(__nv_bfloat162*)&clo[base + 2] = __nv_bfloat162(l2, l3);
    }
}

// ---------------- driver ----------------------------------------------------
static void split_launch(const float* x, bf16* hi, bf16* lo, long long n) {
    int n4 = (int)(n / 4);
    split_kernel<<<(n4 + 255) / 256, 256>>>((const float4*)x, (__nv_bfloat162*)hi, (__nv_bfloat162*)lo, n4);
}

extern "C" void kernel_launch(void* const* d_in, const int* in_sizes, int n_in,
                              void* d_out, int out_size) {
    (void)in_sizes; (void)n_in; (void)out_size;
    const float* tok  = (const float*)d_in[1];
    const float* pos  = (const float*)d_in[2];
    const float* bq   = (const float*)d_in[4];
    const float* bk   = (const float*)d_in[6];
    const float* bv   = (const float*)d_in[8];
    const float* bo   = (const float*)d_in[10];
    const float* b1   = (const float*)d_in[12];
    const float* b2   = (const float*)d_in[14];
    const float* ln1g = (const float*)d_in[15];
    const float* ln1b = (const float*)d_in[16];
    const float* ln2g = (const float*)d_in[17];
    const float* ln2b = (const float*)d_in[18];
    const float* lnfg = (const float*)d_in[19];
    const float* lnfb = (const float*)d_in[20];
    float* out = (float*)d_out;

    float *h, *q, *k, *v;
    cudaGetSymbolAddress((void**)&h, g_h);
    cudaGetSymbolAddress((void**)&q, g_q);
    cudaGetSymbolAddress((void**)&k, g_k);
    cudaGetSymbolAddress((void**)&v, g_v);

    bf16 *tokh, *tokl, *wqh, *wql, *wkh, *wkl, *wvh, *wvl, *woh, *wol;
    bf16 *w1h, *w1l, *w2h, *w2l, *ah, *al, *fh, *fl;
    cudaGetSymbolAddress((void**)&tokh, g_tok_hi); cudaGetSymbolAddress((void**)&tokl, g_tok_lo);
    cudaGetSymbolAddress((void**)&wqh,  g_wq_hi);  cudaGetSymbolAddress((void**)&wql,  g_wq_lo);
    cudaGetSymbolAddress((void**)&wkh,  g_wk_hi);  cudaGetSymbolAddress((void**)&wkl,  g_wk_lo);
    cudaGetSymbolAddress((void**)&wvh,  g_wv_hi);  cudaGetSymbolAddress((void**)&wvl,  g_wv_lo);
    cudaGetSymbolAddress((void**)&woh,  g_wo_hi);  cudaGetSymbolAddress((void**)&wol,  g_wo_lo);
    cudaGetSymbolAddress((void**)&w1h,  g_w1_hi);  cudaGetSymbolAddress((void**)&w1l,  g_w1_lo);
    cudaGetSymbolAddress((void**)&w2h,  g_w2_hi);  cudaGetSymbolAddress((void**)&w2l,  g_w2_lo);
    cudaGetSymbolAddress((void**)&ah,   g_a_hi);   cudaGetSymbolAddress((void**)&al,   g_a_lo);
    cudaGetSymbolAddress((void**)&fh,   g_f_hi);   cudaGetSymbolAddress((void**)&fl,   g_f_lo);

    cudaFuncSetAttribute(mm_gemm<1>, cudaFuncAttributeMaxDynamicSharedMemorySize, GSMEM);
    cudaFuncSetAttribute(mm_gemm<2>, cudaFuncAttributeMaxDynamicSharedMemorySize, GSMEM);
    cudaFuncSetAttribute(mm_gemm<3>, cudaFuncAttributeMaxDynamicSharedMemorySize, GSMEM);
    cudaFuncSetAttribute(qkv_gemm,   cudaFuncAttributeMaxDynamicSharedMemorySize, GSMEM);
    cudaFuncSetAttribute(flash_attn, cudaFuncAttributeMaxDynamicSharedMemorySize, ATT_SMEM);

    // weight splits
    split_launch(tok,                   tokh, tokl, (long long)VV * DD);
    split_launch((const float*)d_in[3],  wqh, wql, (long long)LL * DD * DD);
    split_launch((const float*)d_in[5],  wkh, wkl, (long long)LL * DD * DD);
    split_launch((const float*)d_in[7],  wvh, wvl, (long long)LL * DD * DD);
    split_launch((const float*)d_in[9],  woh, wol, (long long)LL * DD * DD);
    split_launch((const float*)d_in[11], w1h, w1l, (long long)LL * FF * DD);
    split_launch((const float*)d_in[13], w2h, w2l, (long long)LL * DD * FF);

    cvt_x_kernel<<<1, 256>>>((const long long*)d_in[0]);
    embed_kernel<<<(MTOK * DD + 255) / 256, 256>>>(tok, pos);

    dim3 gQKV(18, MTOK / 128);       // (18, 16)
    dim3 gD(DD / 128, MTOK / 128);   // (6, 16)
    dim3 gF(FF / 128, MTOK / 128);   // (24, 16)
    dim3 gV(VV / 128, MTOK / 128);   // (250, 16)
    dim3 gA(SS / 64, HH, BB);        // (16, 12, 2)

    for (int l = 0; l < LL; l++) {
        const size_t wD = (size_t)l * DD * DD;
        ln_kernel<<<MTOK, 256>>>(h, ln1g + l * DD, ln1b + l * DD, ah, al);
        qkv_gemm<<<gQKV, 256, GSMEM>>>(ah, al, wqh + wD, wql + wD, wkh + wD, wkl + wD,
                                       wvh + wD, wvl + wD, bq + l * DD, bk + l * DD,
                                       bv + l * DD, q, k, v);
        flash_attn<<<gA, 128, ATT_SMEM>>>(q, k, v, ah, al);
        mm_gemm<1><<<gD, 256, GSMEM>>>(ah, al, woh + wD, wol + wD, bo + l * DD, h, h,
                                       nullptr, nullptr, DD, DD);
        ln_kernel<<<MTOK, 256>>>(h, ln2g + l * DD, ln2b + l * DD, ah, al);
        mm_gemm<2><<<gF, 256, GSMEM>>>(ah, al, w1h + (size_t)l * FF * DD, w1l + (size_t)l * FF * DD,
                                       b1 + l * FF, nullptr, nullptr, fh, fl, FF, DD);
        mm_gemm<1><<<gD, 256, GSMEM>>>(fh, fl, w2h + (size_t)l * DD * FF, w2l + (size_t)l * DD * FF,
                                       b2 + l * DD, h, h, nullptr, nullptr, DD, FF);
    }

    ln_kernel<<<MTOK, 256>>>(h, lnfg, lnfb, ah, al);
    mm_gemm<3><<<gV, 256, GSMEM>>>(ah, al, tokh, tokl, nullptr, nullptr, out,
                                   nullptr, nullptr, VV, DD);
}

// round 5
// speedup vs baseline: 4.1084x; 1.1462x over previous
#include <cuda_runtime.h>
#include <cuda_bf16.h>
#include <cstdint>
#include <math.h>

#define BB 2
#define SS 1024
#define DD 768
#define HH 12
#define DK 64
#define FF 3072
#define LL 4
#define VV 32000
#define MTOK (BB*SS)   /* 2048 */

typedef __nv_bfloat16 bf16;

// ---------------- scratch ----------------------------------------------------
__device__ float g_h  [MTOK*DD];
__device__ int   g_xi [MTOK];

__device__ bf16 g_tok_hi[VV*DD],    g_tok_lo[VV*DD];
__device__ bf16 g_wq_hi [LL*DD*DD], g_wq_lo [LL*DD*DD];
__device__ bf16 g_wk_hi [LL*DD*DD], g_wk_lo [LL*DD*DD];
__device__ bf16 g_wv_hi [LL*DD*DD], g_wv_lo [LL*DD*DD];
__device__ bf16 g_wo_hi [LL*DD*DD], g_wo_lo [LL*DD*DD];
__device__ bf16 g_w1_hi [LL*FF*DD], g_w1_lo [LL*FF*DD];
__device__ bf16 g_w2_hi [LL*DD*FF], g_w2_lo [LL*DD*FF];
__device__ bf16 g_a_hi  [MTOK*DD],  g_a_lo  [MTOK*DD];
__device__ bf16 g_f_hi  [MTOK*FF],  g_f_lo  [MTOK*FF];
__device__ bf16 g_qh[MTOK*DD], g_ql[MTOK*DD];
__device__ bf16 g_kh[MTOK*DD], g_kl[MTOK*DD];
__device__ bf16 g_vh[MTOK*DD], g_vl[MTOK*DD];

// ---------------- helpers ----------------------------------------------------
__device__ __forceinline__ uint32_t smem_u32(const void* p) {
    uint32_t a;
    asm("{ .reg .u64 t; cvta.to.shared.u64 t, %1; cvt.u32.u64 %0, t; }" : "=r"(a) : "l"(p));
    return a;
}
__device__ __forceinline__ void cpasync16(uint32_t saddr, const void* gaddr) {
    asm volatile("cp.async.cg.shared.global [%0], [%1], 16;" :: "r"(saddr), "l"(gaddr));
}
#define CP_COMMIT() asm volatile("cp.async.commit_group;" ::: "memory")
#define CP_WAIT(N)  asm volatile("cp.async.wait_group %0;" :: "n"(N) : "memory")

__device__ __forceinline__ void ldsm4(uint32_t* r, uint32_t addr) {
    asm volatile("ldmatrix.sync.aligned.m8n8.x4.shared.b16 {%0,%1,%2,%3}, [%4];"
        : "=r"(r[0]), "=r"(r[1]), "=r"(r[2]), "=r"(r[3]) : "r"(addr));
}
__device__ __forceinline__ void ldsm4t(uint32_t* r, uint32_t addr) {
    asm volatile("ldmatrix.sync.aligned.m8n8.x4.trans.shared.b16 {%0,%1,%2,%3}, [%4];"
        : "=r"(r[0]), "=r"(r[1]), "=r"(r[2]), "=r"(r[3]) : "r"(addr));
}
__device__ __forceinline__ void mma16816(float* c, const uint32_t* a, const uint32_t* b) {
    asm volatile(
        "mma.sync.aligned.m16n8k16.row.col.f32.bf16.bf16.f32 "
        "{%0,%1,%2,%3}, {%4,%5,%6,%7}, {%8,%9}, {%0,%1,%2,%3};"
        : "+f"(c[0]), "+f"(c[1]), "+f"(c[2]), "+f"(c[3])
        : "r"(a[0]), "r"(a[1]), "r"(a[2]), "r"(a[3]), "r"(b[0]), "r"(b[1]));
}
__device__ __forceinline__ void split1(float v, bf16& h, bf16& l) {
    h = __float2bfloat16(v);
    l = __float2bfloat16(v - __bfloat162float(h));
}
__device__ __forceinline__ uint32_t packbf(float v0, float v1) {  // lo=v0, hi=v1
    __nv_bfloat162 p(__float2bfloat16(v0), __float2bfloat16(v1));
    return *(uint32_t*)&p;
}

// ---------------- token ids / embed ------------------------------------------
__global__ void cvt_x_kernel(const long long* __restrict__ x64) {
    __shared__ int is64;
    if (threadIdx.x == 0) {
        int ok = 1;
        for (int i = 0; i < 16; i++) { long long t = x64[i]; if (t < 0 || t >= VV) ok = 0; }
        is64 = ok;
    }
    __syncthreads();
    const int* x32 = (const int*)x64;
    if (is64) for (int i = threadIdx.x; i < MTOK; i += blockDim.x) g_xi[i] = (int)x64[i];
    else      for (int i = threadIdx.x; i < MTOK; i += blockDim.x) g_xi[i] = x32[i];
}

__global__ void embed_kernel(const float* __restrict__ tok, const float* __restrict__ pos) {
    int idx = blockIdx.x * blockDim.x + threadIdx.x;
    if (idx < MTOK * DD) {
        int d = idx % DD, t = idx / DD, s = t % SS;
        g_h[idx] = tok[g_xi[t] * DD + d] + pos[s * DD + d];
    }
}

// ---------------- layernorm -> bf16 hi/lo ------------------------------------
__global__ void ln_kernel(const float* __restrict__ in, const float* __restrict__ g,
                          const float* __restrict__ b,
                          bf16* __restrict__ ohi, bf16* __restrict__ olo) {
    int row = blockIdx.x, tid = threadIdx.x;
    const float* xr = in + (size_t)row * DD;
    __shared__ float r1[256], r2[256];
    float s1 = 0.f, s2 = 0.f;
    for (int i = tid; i < DD; i += 256) { float v = xr[i]; s1 += v; s2 += v * v; }
    r1[tid] = s1; r2[tid] = s2;
    __syncthreads();
    for (int o = 128; o > 0; o >>= 1) {
        if (tid < o) { r1[tid] += r1[tid + o]; r2[tid] += r2[tid + o]; }
        __syncthreads();
    }
    float mu = r1[0] * (1.0f / DD);
    float var = r2[0] * (1.0f / DD) - mu * mu;
    float inv = rsqrtf(var + 1e-5f);
    for (int i = tid; i < DD; i += 256) {
        float v = (xr[i] - mu) * inv * g[i] + b[i];
        bf16 h, l; split1(v, h, l);
        ohi[(size_t)row * DD + i] = h;
        olo[(size_t)row * DD + i] = l;
    }
}

// ---------------- fp32 -> bf16 hi/lo split (weights) -------------------------
__global__ void split_kernel(const float4* __restrict__ x,
                             __nv_bfloat162* __restrict__ hi,
                             __nv_bfloat162* __restrict__ lo, int n4) {
    int i = blockIdx.x * blockDim.x + threadIdx.x;
    if (i < n4) {
        float4 v = x[i];
        bf16 hx, lx, hy, ly, hz, lz, hw, lw;
        split1(v.x, hx, lx); split1(v.y, hy, ly);
        split1(v.z, hz, lz); split1(v.w, hw, lw);
        hi[2*i]   = __nv_bfloat162(hx, hy);
        hi[2*i+1] = __nv_bfloat162(hz, hw);
        lo[2*i]   = __nv_bfloat162(lx, ly);
        lo[2*i+1] = __nv_bfloat162(lz, lw);
    }
}

// ---------------- split-bf16 mma.sync GEMM core ------------------------------
#define PADE   40
#define TILEB  (128*PADE*2)
#define STAGEB (4*TILEB)
#define GSMEM  (2*STAGEB)            /* 81920 B */

__device__ __forceinline__ void load_stage(
        uint32_t sbase, int tid,
        const bf16* Ahi, const bf16* Alo, const bf16* Bhi, const bf16* Blo,
        int m0, int n0, int k0, int K) {
    const int c = tid & 3;
    const int r = tid >> 2;
    const bf16* srcs[4] = { Ahi, Alo, Bhi, Blo };
    const int rows0[4] = { m0, m0, n0, n0 };
#pragma unroll
    for (int t = 0; t < 4; t++) {
        uint32_t tb = sbase + t * TILEB;
        const bf16* s = srcs[t];
#pragma unroll
        for (int hrow = 0; hrow < 2; hrow++) {
            int row = r + hrow * 64;
            cpasync16(tb + row * (PADE * 2) + c * 16,
                      s + (size_t)(rows0[t] + row) * K + k0 + c * 8);
        }
    }
}

// EPI: 0 f32+bias, 1 f32+bias+res, 2 bf16split+bias+relu, 3 f32, 4 bf16split+bias+scale
template<int EPI>
__device__ __forceinline__ void gemm_core(
        const bf16* Ahi, const bf16* Alo, const bf16* Bhi, const bf16* Blo,
        const float* bias, const float* res, float sc,
        float* C, bf16* Chi, bf16* Clo,
        int m0, int n0, int N, int K, uint32_t sb) {
    const int tid = threadIdx.x;
    const int wid = tid >> 5, lane = tid & 31;
    const int wm = (wid >> 2) * 64;
    const int wn = (wid & 3) * 32;

    float Cf[4][4][4];
#pragma unroll
    for (int i = 0; i < 4; i++)
#pragma unroll
        for (int j = 0; j < 4; j++)
#pragma unroll
            for (int x = 0; x < 4; x++) Cf[i][j][x] = 0.f;

    const int NS = K >> 5;
    const int a_row = (lane & 15);
    const int a_colsel = (lane >> 4) * 8;
    const int b_row = (lane & 7) + ((lane >> 4) & 1) * 8;
    const int b_colsel = ((lane >> 3) & 1) * 8;

    load_stage(sb, tid, Ahi, Alo, Bhi, Blo, m0, n0, 0, K);
    CP_COMMIT();

    for (int s = 0; s < NS; s++) {
        if (s + 1 < NS) {
            load_stage(sb + ((s + 1) & 1) * STAGEB, tid, Ahi, Alo, Bhi, Blo,
                       m0, n0, (s + 1) << 5, K);
            CP_COMMIT();
            CP_WAIT(1);
        } else {
            CP_WAIT(0);
        }
        __syncthreads();

        const uint32_t st = sb + (s & 1) * STAGEB;
        const uint32_t tAh = st;
        const uint32_t tAl = st + TILEB;
        const uint32_t tBh = st + 2 * TILEB;
        const uint32_t tBl = st + 3 * TILEB;

#pragma unroll
        for (int k16 = 0; k16 < 32; k16 += 16) {
            uint32_t Af[4][4], Bf[2][4];
#pragma unroll
            for (int mf = 0; mf < 4; mf++)
                ldsm4(Af[mf], tAh + (wm + mf * 16 + a_row) * (PADE * 2) + (k16 + a_colsel) * 2);
#pragma unroll
            for (int p = 0; p < 2; p++)
                ldsm4(Bf[p], tBh + (wn + p * 16 + b_row) * (PADE * 2) + (k16 + b_colsel) * 2);
#pragma unroll
            for (int mf = 0; mf < 4; mf++)
#pragma unroll
                for (int nf = 0; nf < 4; nf++)
                    mma16816(Cf[mf][nf], Af[mf], &Bf[nf >> 1][(nf & 1) * 2]);
#pragma unroll
            for (int p = 0; p < 2; p++)
                ldsm4(Bf[p], tBl + (wn + p * 16 + b_row) * (PADE * 2) + (k16 + b_colsel) * 2);
#pragma unroll
            for (int mf = 0; mf < 4; mf++)
#pragma unroll
                for (int nf = 0; nf < 4; nf++)
                    mma16816(Cf[mf][nf], Af[mf], &Bf[nf >> 1][(nf & 1) * 2]);
#pragma unroll
            for (int mf = 0; mf < 4; mf++)
                ldsm4(Af[mf], tAl + (wm + mf * 16 + a_row) * (PADE * 2) + (k16 + a_colsel) * 2);
#pragma unroll
            for (int p = 0; p < 2; p++)
                ldsm4(Bf[p], tBh + (wn + p * 16 + b_row) * (PADE * 2) + (k16 + b_colsel) * 2);
#pragma unroll
            for (int mf = 0; mf < 4; mf++)
#pragma unroll
                for (int nf = 0; nf < 4; nf++)
                    mma16816(Cf[mf][nf], Af[mf], &Bf[nf >> 1][(nf & 1) * 2]);
        }
        __syncthreads();
    }

    const int g = lane >> 2, t2 = (lane & 3) * 2;
#pragma unroll
    for (int mf = 0; mf < 4; mf++) {
#pragma unroll
        for (int nf = 0; nf < 4; nf++) {
            int n = n0 + wn + nf * 8 + t2;
#pragma unroll
            for (int hrow = 0; hrow < 2; hrow++) {
                int m = m0 + wm + mf * 16 + g + hrow * 8;
                float v0 = Cf[mf][nf][hrow * 2 + 0];
                float v1 = Cf[mf][nf][hrow * 2 + 1];
                if (EPI != 3) { v0 += bias[n]; v1 += bias[n + 1]; }
                if (EPI == 2 || EPI == 4) {
                    if (EPI == 2) { v0 = fmaxf(v0, 0.f); v1 = fmaxf(v1, 0.f); }
                    else          { v0 *= sc; v1 *= sc; }
                    bf16 h0, l0, h1, l1;
                    split1(v0, h0, l0); split1(v1, h1, l1);
                    *(__nv_bfloat162*)&Chi[(size_t)m * N + n] = __nv_bfloat162(h0, h1);
                    *(__nv_bfloat162*)&Clo[(size_t)m * N + n] = __nv_bfloat162(l0, l1);
                } else {
                    if (EPI == 1) {
                        const float2 rr = *(const float2*)&res[(size_t)m * N + n];
                        v0 += rr.x; v1 += rr.y;
                    }
                    *(float2*)&C[(size_t)m * N + n] = make_float2(v0, v1);
                }
            }
        }
    }
}

template<int EPI>
__global__ __launch_bounds__(256, 2)
void mm_gemm(const bf16* __restrict__ Ahi, const bf16* __restrict__ Alo,
             const bf16* __restrict__ Bhi, const bf16* __restrict__ Blo,
             const float* __restrict__ bias, const float* __restrict__ res,
             float* __restrict__ C, bf16* __restrict__ Chi, bf16* __restrict__ Clo,
             int N, int K) {
    extern __shared__ char smem_raw[];
    gemm_core<EPI>(Ahi, Alo, Bhi, Blo, bias, res, 1.0f, C, Chi, Clo,
                   blockIdx.y * 128, blockIdx.x * 128, N, K, smem_u32(smem_raw));
}

// fused QKV -> bf16 hi/lo outputs; q scaled by 1/8
__global__ __launch_bounds__(256, 2)
void qkv_gemm(const bf16* __restrict__ Ahi, const bf16* __restrict__ Alo,
              const bf16* __restrict__ wqh, const bf16* __restrict__ wql,
              const bf16* __restrict__ wkh, const bf16* __restrict__ wkl,
              const bf16* __restrict__ wvh, const bf16* __restrict__ wvl,
              const float* __restrict__ bq, const float* __restrict__ bk,
              const float* __restrict__ bv,
              bf16* __restrict__ qh, bf16* __restrict__ ql,
              bf16* __restrict__ kh, bf16* __restrict__ kl,
              bf16* __restrict__ vh, bf16* __restrict__ vl) {
    extern __shared__ char smem_raw[];
    const int which = blockIdx.x / 6, nb = blockIdx.x % 6;
    const bf16* Bh = (which == 0) ? wqh : (which == 1) ? wkh : wvh;
    const bf16* Bl = (which == 0) ? wql : (which == 1) ? wkl : wvl;
    const float* bias = (which == 0) ? bq : (which == 1) ? bk : bv;
    bf16* Ch = (which == 0) ? qh : (which == 1) ? kh : vh;
    bf16* Cl = (which == 0) ? ql : (which == 1) ? kl : vl;
    float sc = (which == 0) ? 0.125f : 1.0f;
    gemm_core<4>(Ahi, Alo, Bh, Bl, bias, nullptr, sc, nullptr, Ch, Cl,
                 blockIdx.y * 128, nb * 128, DD, DD, smem_u32(smem_raw));
}

// ---------------- MMA flash attention ---------------------------------------
// CTA: 64 q-rows x (head, batch). 4 warps, each 16 rows x 64 cols.
// Split-bf16 3-pass for QK and PV; fp32 online softmax in fragments.
#define AST 144                       /* padded row stride bytes (72 bf16) */
#define ATILE (64*AST)                /* 9216 B */
#define ATT_SMEM (2*ATILE + 2*4*ATILE)  /* Qh,Ql + 2 KV buffers = 92160 B */

__device__ __forceinline__ void att_load4(uint32_t dst, const bf16* src,
                                          size_t grow0, int hcol, int tid) {
    int r = tid >> 1, c0 = (tid & 1) * 4;
    const bf16* p = src + (grow0 + r) * DD + hcol + c0 * 8;
    uint32_t d = dst + r * AST + c0 * 16;
#pragma unroll
    for (int i = 0; i < 4; i++) cpasync16(d + i * 16, p + i * 8);
}

__global__ __launch_bounds__(128)
void flash_attn(const bf16* __restrict__ qh, const bf16* __restrict__ ql,
                const bf16* __restrict__ kh, const bf16* __restrict__ kl,
                const bf16* __restrict__ vh, const bf16* __restrict__ vl,
                bf16* __restrict__ chi, bf16* __restrict__ clo) {
    const int qt = gridDim.x - 1 - blockIdx.x;   // heavy tiles first
    const int hd = blockIdx.y, b = blockIdx.z;
    extern __shared__ char smc[];
    const uint32_t sb = smem_u32(smc);
    const uint32_t Qh_s = sb, Ql_s = sb + ATILE;
    const uint32_t KV = sb + 2 * ATILE;

    const int tid = threadIdx.x, wid = tid >> 5, lane = tid & 31;
    const size_t qrow0 = (size_t)(b * SS + qt * 64);
    const int hcol = hd * DK;

    att_load4(Qh_s, qh, qrow0, hcol, tid);
    att_load4(Ql_s, ql, qrow0, hcol, tid);
    {
        size_t kr = (size_t)(b * SS);
        att_load4(KV + 0 * ATILE, kh, kr, hcol, tid);
        att_load4(KV + 1 * ATILE, kl, kr, hcol, tid);
        att_load4(KV + 2 * ATILE, vh, kr, hcol, tid);
        att_load4(KV + 3 * ATILE, vl, kr, hcol, tid);
    }
    CP_COMMIT();

    float O[8][4];
    float mrow[2] = { -1e30f, -1e30f };
    float lrow[2] = { 0.f, 0.f };
#pragma unroll
    for (int nt = 0; nt < 8; nt++)
#pragma unroll
        for (int x = 0; x < 4; x++) O[nt][x] = 0.f;

    const int g = lane >> 2, t2q = (lane & 3) * 2;
    const int a_row = wid * 16 + (lane & 15);
    const uint32_t a_cs = ((lane >> 4) << 3) * 2;
    const int b_row = (lane & 7) + (((lane >> 4) & 1) << 3);
    const uint32_t b_cs = (((lane >> 3) & 1) << 3) * 2;
    const int v_row = (lane & 15);
    const uint32_t v_cs = ((lane >> 4) << 3) * 2;

    for (int jt = 0; jt <= qt; jt++) {
        if (jt < qt) {
            size_t kr = (size_t)(b * SS + (jt + 1) * 64);
            uint32_t nb = KV + ((jt + 1) & 1) * (4 * ATILE);
            att_load4(nb + 0 * ATILE, kh, kr, hcol, tid);
            att_load4(nb + 1 * ATILE, kl, kr, hcol, tid);
            att_load4(nb + 2 * ATILE, vh, kr, hcol, tid);
            att_load4(nb + 3 * ATILE, vl, kr, hcol, tid);
            CP_COMMIT();
            CP_WAIT(1);
        } else {
            CP_WAIT(0);
        }
        __syncthreads();

        const uint32_t Kh_s = KV + (jt & 1) * (4 * ATILE);
        const uint32_t Kl_s = Kh_s + ATILE;
        const uint32_t Vh_s = Kl_s + ATILE;
        const uint32_t Vl_s = Vh_s + ATILE;

        // ---- scores S = Q @ K^T (3-pass split) ----
        float S[8][4];
#pragma unroll
        for (int nt = 0; nt < 8; nt++)
#pragma unroll
            for (int x = 0; x < 4; x++) S[nt][x] = 0.f;

#pragma unroll
        for (int ks = 0; ks < 4; ks++) {
            uint32_t Ah[4], Al[4];
            ldsm4(Ah, Qh_s + a_row * AST + ks * 32 + a_cs);
            ldsm4(Al, Ql_s + a_row * AST + ks * 32 + a_cs);
#pragma unroll
            for (int p = 0; p < 2; p++) {
                uint32_t Bh4[4], Bl4[4];
                ldsm4(Bh4, Kh_s + (p * 16 + b_row) * AST + ks * 32 + b_cs);
                ldsm4(Bl4, Kl_s + (p * 16 + b_row) * AST + ks * 32 + b_cs);
#pragma unroll
                for (int q = 0; q < 2; q++) {
                    mma16816(S[p * 2 + q], Ah, &Bh4[q * 2]);
                    mma16816(S[p * 2 + q], Ah, &Bl4[q * 2]);
                    mma16816(S[p * 2 + q], Al, &Bh4[q * 2]);
                }
                uint32_t Bh4b[4], Bl4b[4];
                ldsm4(Bh4b, Kh_s + ((p + 2) * 16 + b_row) * AST + ks * 32 + b_cs);
                ldsm4(Bl4b, Kl_s + ((p + 2) * 16 + b_row) * AST + ks * 32 + b_cs);
#pragma unroll
                for (int q = 0; q < 2; q++) {
                    mma16816(S[(p + 2) * 2 + q], Ah, &Bh4b[q * 2]);
                    mma16816(S[(p + 2) * 2 + q], Ah, &Bl4b[q * 2]);
                    mma16816(S[(p + 2) * 2 + q], Al, &Bh4b[q * 2]);
                }
            }
        }

        // ---- online softmax (per row halves g, g+8) ----
        const bool diag = (jt == qt);
#pragma unroll
        for (int half = 0; half < 2; half++) {
            const int rloc = wid * 16 + g + half * 8;
            float mt = -1e30f;
#pragma unroll
            for (int nt = 0; nt < 8; nt++) {
                float s0 = S[nt][half * 2], s1 = S[nt][half * 2 + 1];
                if (diag) {
                    if (nt * 8 + t2q > rloc)     s0 = -1e30f;
                    if (nt * 8 + t2q + 1 > rloc) s1 = -1e30f;
                }
                S[nt][half * 2] = s0; S[nt][half * 2 + 1] = s1;
                mt = fmaxf(mt, fmaxf(s0, s1));
            }
            mt = fmaxf(mt, __shfl_xor_sync(0xffffffffu, mt, 1));
            mt = fmaxf(mt, __shfl_xor_sync(0xffffffffu, mt, 2));
            float mn = fmaxf(mrow[half], mt);
            float f = __expf(mrow[half] - mn);
            mrow[half] = mn;
            float rs = 0.f;
#pragma unroll
            for (int nt = 0; nt < 8; nt++) {
                float e0 = __expf(S[nt][half * 2] - mn);
                float e1 = __expf(S[nt][half * 2 + 1] - mn);
                S[nt][half * 2] = e0; S[nt][half * 2 + 1] = e1;
                rs += e0 + e1;
            }
            rs += __shfl_xor_sync(0xffffffffu, rs, 1);
            rs += __shfl_xor_sync(0xffffffffu, rs, 2);
            lrow[half] = lrow[half] * f + rs;
#pragma unroll
            for (int nt = 0; nt < 8; nt++) {
                O[nt][half * 2] *= f; O[nt][half * 2 + 1] *= f;
            }
        }

        // ---- O += P @ V (3-pass split; P from fragments) ----
#pragma unroll
        for (int ks = 0; ks < 4; ks++) {
            uint32_t Ph[4], Pl[4];
#pragma unroll
            for (int q4 = 0; q4 < 4; q4++) {
                int tile = 2 * ks + (q4 >> 1);
                int o = (q4 & 1) * 2;
                float v0 = S[tile][o], v1 = S[tile][o + 1];
                bf16 h0 = __float2bfloat16(v0), h1 = __float2bfloat16(v1);
                __nv_bfloat162 hh(h0, h1);
                Ph[q4] = *(uint32_t*)&hh;
                Pl[q4] = packbf(v0 - __bfloat162float(h0), v1 - __bfloat162float(h1));
            }
#pragma unroll
            for (int nt = 0; nt < 4; nt++) {
                uint32_t Vh4[4], Vl4[4];
                ldsm4t(Vh4, Vh_s + (ks * 16 + v_row) * AST + nt * 32 + v_cs);
                ldsm4t(Vl4, Vl_s + (ks * 16 + v_row) * AST + nt * 32 + v_cs);
#pragma unroll
                for (int q = 0; q < 2; q++) {
                    mma16816(O[nt * 2 + q], Ph, &Vh4[q * 2]);
                    mma16816(O[nt * 2 + q], Ph, &Vl4[q * 2]);
                    mma16816(O[nt * 2 + q], Pl, &Vh4[q * 2]);
                }
            }
        }
        __syncthreads();
    }

    // ---- epilogue: O / l -> bf16 hi/lo ----
    float inv[2] = { 1.0f / lrow[0], 1.0f / lrow[1] };
#pragma unroll
    for (int nt = 0; nt < 8; nt++) {
#pragma unroll
        for (int half = 0; half < 2; half++) {
            size_t row = qrow0 + wid * 16 + g + half * 8;
            int col = hcol + nt * 8 + t2q;
            float v0 = O[nt][half * 2] * inv[half];
            float v1 = O[nt][half * 2 + 1] * inv[half];
            bf16 h0, l0, h1, l1;
            split1(v0, h0, l0); split1(v1, h1, l1);
            *(__nv_bfloat162*)&chi[row * DD + col] = __nv_bfloat162(h0, h1);
            *(__nv_bfloat162*)&clo[row * DD + col] = __nv_bfloat162(l0, l1);
        }
    }
}

// ---------------- driver -----------------------------------------------------
static void split_launch(const float* x, bf16* hi, bf16* lo, long long n) {
    int n4 = (int)(n / 4);
    split_kernel<<<(n4 + 255) / 256, 256>>>((const float4*)x, (__nv_bfloat162*)hi, (__nv_bfloat162*)lo, n4);
}

extern "C" void kernel_launch(void* const* d_in, const int* in_sizes, int n_in,
                              void* d_out, int out_size) {
    (void)in_sizes; (void)n_in; (void)out_size;
    const float* tok  = (const float*)d_in[1];
    const float* pos  = (const float*)d_in[2];
    const float* bq   = (const float*)d_in[4];
    const float* bk   = (const float*)d_in[6];
    const float* bv   = (const float*)d_in[8];
    const float* bo   = (const float*)d_in[10];
    const float* b1   = (const float*)d_in[12];
    const float* b2   = (const float*)d_in[14];
    const float* ln1g = (const float*)d_in[15];
    const float* ln1b = (const float*)d_in[16];
    const float* ln2g = (const float*)d_in[17];
    const float* ln2b = (const float*)d_in[18];
    const float* lnfg = (const float*)d_in[19];
    const float* lnfb = (const float*)d_in[20];
    float* out = (float*)d_out;

    float *h;
    cudaGetSymbolAddress((void**)&h, g_h);

    bf16 *tokh, *tokl, *wqh, *wql, *wkh, *wkl, *wvh, *wvl, *woh, *wol;
    bf16 *w1h, *w1l, *w2h, *w2l, *ah, *al, *fh, *fl;
    bf16 *qh_, *ql_, *kh_, *kl_, *vh_, *vl_;
    cudaGetSymbolAddress((void**)&tokh, g_tok_hi); cudaGetSymbolAddress((void**)&tokl, g_tok_lo);
    cudaGetSymbolAddress((void**)&wqh,  g_wq_hi);  cudaGetSymbolAddress((void**)&wql,  g_wq_lo);
    cudaGetSymbolAddress((void**)&wkh,  g_wk_hi);  cudaGetSymbolAddress((void**)&wkl,  g_wk_lo);
    cudaGetSymbolAddress((void**)&wvh,  g_wv_hi);  cudaGetSymbolAddress((void**)&wvl,  g_wv_lo);
    cudaGetSymbolAddress((void**)&woh,  g_wo_hi);  cudaGetSymbolAddress((void**)&wol,  g_wo_lo);
    cudaGetSymbolAddress((void**)&w1h,  g_w1_hi);  cudaGetSymbolAddress((void**)&w1l,  g_w1_lo);
    cudaGetSymbolAddress((void**)&w2h,  g_w2_hi);  cudaGetSymbolAddress((void**)&w2l,  g_w2_lo);
    cudaGetSymbolAddress((void**)&ah,   g_a_hi);   cudaGetSymbolAddress((void**)&al,   g_a_lo);
    cudaGetSymbolAddress((void**)&fh,   g_f_hi);   cudaGetSymbolAddress((void**)&fl,   g_f_lo);
    cudaGetSymbolAddress((void**)&qh_,  g_qh);     cudaGetSymbolAddress((void**)&ql_,  g_ql);
    cudaGetSymbolAddress((void**)&kh_,  g_kh);     cudaGetSymbolAddress((void**)&kl_,  g_kl);
    cudaGetSymbolAddress((void**)&vh_,  g_vh);     cudaGetSymbolAddress((void**)&vl_,  g_vl);

    cudaFuncSetAttribute(mm_gemm<1>, cudaFuncAttributeMaxDynamicSharedMemorySize, GSMEM);
    cudaFuncSetAttribute(mm_gemm<2>, cudaFuncAttributeMaxDynamicSharedMemorySize, GSMEM);
    cudaFuncSetAttribute(mm_gemm<3>, cudaFuncAttributeMaxDynamicSharedMemorySize, GSMEM);
    cudaFuncSetAttribute(qkv_gemm,   cudaFuncAttributeMaxDynamicSharedMemorySize, GSMEM);
    cudaFuncSetAttribute(flash_attn, cudaFuncAttributeMaxDynamicSharedMemorySize, ATT_SMEM);

    split_launch(tok,                   tokh, tokl, (long long)VV * DD);
    split_launch((const float*)d_in[3],  wqh, wql, (long long)LL * DD * DD);
    split_launch((const float*)d_in[5],  wkh, wkl, (long long)LL * DD * DD);
    split_launch((const float*)d_in[7],  wvh, wvl, (long long)LL * DD * DD);
    split_launch((const float*)d_in[9],  woh, wol, (long long)LL * DD * DD);
    split_launch((const float*)d_in[11], w1h, w1l, (long long)LL * FF * DD);
    split_launch((const float*)d_in[13], w2h, w2l, (long long)LL * DD * FF);

    cvt_x_kernel<<<1, 256>>>((const long long*)d_in[0]);
    embed_kernel<<<(MTOK * DD + 255) / 256, 256>>>(tok, pos);

    dim3 gQKV(18, MTOK / 128);
    dim3 gD(DD / 128, MTOK / 128);
    dim3 gF(FF / 128, MTOK / 128);
    dim3 gV(VV / 128, MTOK / 128);
    dim3 gA(SS / 64, HH, BB);

    for (int l = 0; l < LL; l++) {
        const size_t wD = (size_t)l * DD * DD;
        ln_kernel<<<MTOK, 256>>>(h, ln1g + l * DD, ln1b + l * DD, ah, al);
        qkv_gemm<<<gQKV, 256, GSMEM>>>(ah, al, wqh + wD, wql + wD, wkh + wD, wkl + wD,
                                       wvh + wD, wvl + wD, bq + l * DD, bk + l * DD,
                                       bv + l * DD, qh_, ql_, kh_, kl_, vh_, vl_);
        flash_attn<<<gA, 128, ATT_SMEM>>>(qh_, ql_, kh_, kl_, vh_, vl_, ah, al);
        mm_gemm<1><<<gD, 256, GSMEM>>>(ah, al, woh + wD, wol + wD, bo + l * DD, h, h,
                                       nullptr, nullptr, DD, DD);
        ln_kernel<<<MTOK, 256>>>(h, ln2g + l * DD, ln2b + l * DD, ah, al);
        mm_gemm<2><<<gF, 256, GSMEM>>>(ah, al, w1h + (size_t)l * FF * DD, w1l + (size_t)l * FF * DD,
                                       b1 + l * FF, nullptr, nullptr, fh, fl, FF, DD);
        mm_gemm<1><<<gD, 256, GSMEM>>>(fh, fl, w2h + (size_t)l * DD * FF, w2l + (size_t)l * DD * FF,
                                       b2 + l * DD, h, h, nullptr, nullptr, DD, FF);
    }

    ln_kernel<<<MTOK, 256>>>(h, lnfg, lnfb, ah, al);
    mm_gemm<3><<<gV, 256, GSMEM>>>(ah, al, tokh, tokl, nullptr, nullptr, out,
                                   nullptr, nullptr, VV, DD);
}